// round 15
// baseline (speedup 1.0000x reference)
#include <cuda_runtime.h>
#include <cuda_bf16.h>
#include <cstdint>

// ---------------- problem constants ----------------
#define BQ 2
#define TQ 8
#define YQ 128
#define XQ 128
#define CIN 128
#define COUTQ 64
#define YOQ 255
#define XOQ 255
#define NPTS 262144
#define NCELL (BQ*TQ*YQ*XQ)
#define NSITE (BQ*TQ*YOQ*XOQ)
#define NSLAB (BQ*TQ*YQ)
#define EPSQ 1e-5f

// ---------------- device scratch ----------------
// fp32 cell features stored DIRECTLY in the swizzled quarter-image layout:
// [slab][kq 0..3][cell*128 + swz8(c8, cell&7)] (16KB per quarter, 64KB per slab)
__device__ __align__(16) float g_Ab[(size_t)NSLAB * 16384];
__device__ __align__(16) int   g_occ[NCELL];
__device__ unsigned char       g_mask[NSITE];
__device__ __align__(16) float g_sum[COUTQ];
__device__ __align__(16) float g_sumsq[COUTQ];
__device__ int                 g_nactive;
__device__ __align__(16) float g_scale[COUTQ];
__device__ __align__(16) float g_shift[COUTQ];
// pre-swizzled tf32 W images: [ktky 0..8][kq 0..3][kx 0..2][co*128 + swz8] (24KB per (ktky,kq))
__device__ __align__(16) unsigned char g_Wt[9 * 4 * 3 * 8192];

// ---------------- helpers ----------------
__device__ __forceinline__ uint32_t smem_u32(const void* p) {
    uint32_t a;
    asm("{ .reg .u64 t; cvta.to.shared.u64 t, %1; cvt.u32.u64 %0, t; }" : "=r"(a) : "l"(p));
    return a;
}
__device__ __forceinline__ void ldsm4(uint32_t* r, uint32_t addr) {
    asm volatile("ldmatrix.sync.aligned.m8n8.x4.shared.b16 {%0,%1,%2,%3}, [%4];"
        : "=r"(r[0]), "=r"(r[1]), "=r"(r[2]), "=r"(r[3]) : "r"(addr));
}
__device__ __forceinline__ void mma_tf32(float* c, const uint32_t* a, uint32_t b0, uint32_t b1) {
    asm volatile("mma.sync.aligned.m16n8k8.row.col.f32.tf32.tf32.f32 "
        "{%0,%1,%2,%3}, {%4,%5,%6,%7}, {%8,%9}, {%0,%1,%2,%3};"
        : "+f"(c[0]), "+f"(c[1]), "+f"(c[2]), "+f"(c[3])
        : "r"(a[0]), "r"(a[1]), "r"(a[2]), "r"(a[3]), "r"(b0), "r"(b1));
}
__device__ __forceinline__ uint32_t f2tf32(float x) {
    uint32_t t;
    asm("cvt.rna.tf32.f32 %0, %1;" : "=r"(t) : "f"(x));
    return t;
}
__device__ __forceinline__ void bulkcp(uint32_t dst, const void* src, uint32_t bytes, uint32_t mbar) {
    asm volatile("cp.async.bulk.shared::cluster.global.mbarrier::complete_tx::bytes "
                 "[%0], [%1], %2, [%3];"
                 :: "r"(dst), "l"(src), "r"(bytes), "r"(mbar) : "memory");
}
#define MBARRIER_INIT(addr, cnt) \
    asm volatile("mbarrier.init.shared.b64 [%0], %1;" :: "r"((uint32_t)(addr)), "r"((uint32_t)(cnt)) : "memory")
#define MBARRIER_EXPECT_TX(addr, tx) \
    asm volatile("mbarrier.arrive.expect_tx.shared.b64 _, [%0], %1;" \
        :: "r"((uint32_t)(addr)), "r"((uint32_t)(tx)) : "memory")
#define MBARRIER_ARRIVE(addr) \
    asm volatile("mbarrier.arrive.shared.b64 _, [%0];" :: "r"((uint32_t)(addr)) : "memory")
#define MBARRIER_WAIT_PARITY(addr, par) do { \
    uint32_t _m = (uint32_t)(addr); uint32_t _p = (uint32_t)(par); uint32_t _d; \
    asm volatile("{\n\t.reg .pred p;\n\tmbarrier.try_wait.parity.acquire.cta.shared::cta.b64 p, [%1], %2;\n\tselp.b32 %0, 1, 0, p;\n\t}" \
        : "=r"(_d) : "r"(_m), "r"(_p) : "memory"); \
    if (!_d) { \
        asm volatile("{\n\t.reg .pred P1;\n\tWL_%=:\n\tmbarrier.try_wait.parity.acquire.cta.shared::cta.b64 P1, [%0], %1, 0x989680;\n\t@P1 bra.uni WD_%=;\n\tbra.uni WL_%=;\n\tWD_%=:\n\t}" \
            :: "r"(_m), "r"(_p) : "memory"); \
    } } while (0)

// 128B rows of 8 16B-chunks, XOR-swizzled.
__device__ __forceinline__ uint32_t swz8(int c8, int rs) {
    return (uint32_t)(((c8 ^ rs) & 7) << 4);
}

// ---------------- K0: zero scratch (g_Ab in image layout) + prep W images ----------------
__global__ void k_zero(const float* __restrict__ W) {
    int idx = blockIdx.x * 256 + threadIdx.x;
    if (idx < NCELL * CIN / 4)
        ((float4*)g_Ab)[idx] = make_float4(0.f, 0.f, 0.f, 0.f);
    if (idx < NCELL / 4)
        ((int4*)g_occ)[idx] = make_int4(0, 0, 0, 0);
    if (idx < COUTQ) { g_sum[idx] = 0.f; g_sumsq[idx] = 0.f; }
    if (idx == 0) g_nactive = 0;
    if (idx < 27 * COUTQ * 32) {
        int koff = idx >> 11;
        int r    = idx & 2047;
        int co = r >> 5, c32 = r & 31;
        int kq = c32 >> 3, c8 = c32 & 7;
        int ktky = koff / 3, kx = koff % 3;
        uint32_t v[4];
#pragma unroll
        for (int j = 0; j < 4; j++) {
            int ci = c32 * 4 + j;
            v[j] = f2tf32(W[((size_t)koff * CIN + ci) * COUTQ + co]);
        }
        uint32_t dst = (uint32_t)(((ktky * 4 + kq) * 3 + kx) * 8192)
                     + (uint32_t)(co * 128) + swz8(c8, co & 7);
        *(uint4*)(g_Wt + dst) = make_uint4(v[0], v[1], v[2], v[3]);
    }
}

// ---------------- K1: scatter points directly into swizzled image ----------------
__global__ void k_scatter(const float* __restrict__ feats,
                          const int* __restrict__ cb, const int* __restrict__ ct,
                          const int* __restrict__ cy, const int* __restrict__ cx) {
    int i = blockIdx.x * 256 + threadIdx.x;
    if (i >= NPTS * 32) return;
    int p  = i >> 5;
    int c4 = i & 31;
    int slab = (cb[p] * TQ + ct[p]) * YQ + cy[p];
    int cell = cx[p];
    float4 v = ((const float4*)feats)[p * 32 + c4];
    int kq = c4 >> 3, c8 = c4 & 7;
    float* dst = g_Ab + (size_t)slab * 16384 + kq * 4096
               + cell * 32 + (swz8(c8, cell & 7) >> 2);
    atomicAdd(dst + 0, v.x);
    atomicAdd(dst + 1, v.y);
    atomicAdd(dst + 2, v.z);
    atomicAdd(dst + 3, v.w);
    if (c4 == 0) atomicAdd(&g_occ[slab * XQ + cell], 1);
}

// ---------------- K2: occ-2, quarter-stage bulk-copy tf32 conv ----------------
// Stage (40KB): A-quarter [0,16K), W [16K,40K) (kx stride 8K). 2 buffers.
// NEW: no shifted a1 fragment; kx=0 contributions accumulate into accP over the
// warp's OWN rows and are row-shifted once at the epilogue (shuffles + smem stage).
#define STG 40960
#define CONV_DYN_SMEM (2 * STG)

__global__ void __launch_bounds__(256, 2) k_conv(float* __restrict__ out) {
    extern __shared__ char smem[];
    __shared__ __align__(8) uint64_t mb[4];   // full0, full1, empty0, empty1
    __shared__ float stageP[8][32];           // boundary row exchange (warp wid -> wid-2)
    const uint32_t sb = smem_u32(smem);
    const uint32_t mbF0 = smem_u32(&mb[0]), mbF1 = smem_u32(&mb[1]);
    const uint32_t mbE0 = smem_u32(&mb[2]), mbE1 = smem_u32(&mb[3]);
    const int tid = threadIdx.x, wid = tid >> 5, lane = tid & 31;
    const int half = wid & 1, wm = wid >> 1;

    const int bid = blockIdx.x;
    const int oy = bid % YOQ;
    const int bt = bid / YOQ;
    const int b = bt >> 3, ot = bt & 7;

    // y taps
    int nky, cys[2], kys[2];
    if ((oy & 1) == 0) { nky = 1; cys[0] = oy >> 1;       kys[0] = 1; }
    else               { nky = 2; cys[0] = (oy + 1) >> 1; kys[0] = 0;
                                  cys[1] = (oy - 1) >> 1; kys[1] = 2; }

    // iteration list
    int nIter = 0, slabI[6], ktkyI[6];
    for (int kt = 0; kt < 3; kt++) {
        int ctv = ot + 1 - kt;
        if (ctv < 0 || ctv >= TQ) continue;
        for (int yt = 0; yt < nky; yt++) {
            slabI[nIter] = (b * TQ + ctv) * YQ + cys[yt];
            ktkyI[nIter] = kt * 3 + kys[yt];
            nIter++;
        }
    }
    const int nStage = nIter * 4;

    if (tid == 0) {
        MBARRIER_INIT(mbF0, 1); MBARRIER_INIT(mbF1, 1);
        MBARRIER_INIT(mbE0, 8); MBARRIER_INIT(mbE1, 8);
    }
    __syncthreads();

    // ldmatrix geometry (128B rows)
    const int r0 = wm << 5;
    const int matL = lane >> 3, rr = lane & 7;
    const int cSel = matL >> 1;
    int rowA0[2];
    rowA0[0] = r0 + rr + ((matL & 1) << 3);
    rowA0[1] = rowA0[0] + 16;
    const uint32_t bA0[2] = { (uint32_t)rowA0[0] * 128, (uint32_t)rowA0[1] * 128 };
    const int rs0[2] = { rowA0[0] & 7, rowA0[1] & 7 };
    const int rowB = half * 32 + rr + ((matL & 1) << 3);
    const uint32_t bB0 = (uint32_t)rowB * 128;
    const uint32_t bB1 = bB0 + 16 * 128;
    const int rsB = rowB & 7;

    float accE[2][4][4], accO[2][4][4], accP[2][4][4];
#pragma unroll
    for (int mt = 0; mt < 2; mt++)
#pragma unroll
        for (int i = 0; i < 4; i++)
#pragma unroll
            for (int j = 0; j < 4; j++) {
                accE[mt][i][j] = 0.f; accO[mt][i][j] = 0.f; accP[mt][i][j] = 0.f;
            }

#define FETCH(ST, DST, MBAR) do { \
    int _it = (ST) >> 2, _kq = (ST) & 3; \
    MBARRIER_EXPECT_TX(MBAR, STG); \
    bulkcp((DST),         (const char*)g_Ab + (size_t)slabI[_it] * 65536 + _kq * 16384, 16384, MBAR); \
    bulkcp((DST) + 16384, g_Wt + (size_t)(ktkyI[_it] * 4 + _kq) * 24576,   24576, MBAR); \
} while (0)

    if (tid == 0) {
        FETCH(0, sb, mbF0);
        FETCH(1, sb + STG, mbF1);
    }

    int phF0 = 0, phF1 = 0, phE0 = 0, phE1 = 0;
    for (int st = 0; st < nStage; st++) {
        const int buf = st & 1;
        const uint32_t S = sb + (uint32_t)buf * STG;
        if (buf) { MBARRIER_WAIT_PARITY(mbF1, phF1); phF1 ^= 1; }
        else     { MBARRIER_WAIT_PARITY(mbF0, phF0); phF0 ^= 1; }

        const uint32_t W0 = S + 16384;            // kx=0
        const uint32_t W1 = S + 16384 + 8192;     // kx=1
        const uint32_t W2 = S + 16384 + 16384;    // kx=2
#pragma unroll
        for (int s = 0; s < 4; s++) {
            int ck = 2 * s + cSel;
            uint32_t a0[2][4];
            ldsm4(a0[0], S + bA0[0] + swz8(ck, rs0[0]));
            ldsm4(a0[1], S + bA0[1] + swz8(ck, rs0[1]));
            uint32_t ob = swz8(ck, rsB);
            {   // kx=1 -> even sites
                uint32_t bf[8];
                ldsm4(bf,     W1 + bB0 + ob);
                ldsm4(bf + 4, W1 + bB1 + ob);
#pragma unroll
                for (int j2 = 0; j2 < 2; j2++)
#pragma unroll
                    for (int mt = 0; mt < 2; mt++) {
                        mma_tf32(accE[mt][2 * j2],     a0[mt], bf[4 * j2],     bf[4 * j2 + 2]);
                        mma_tf32(accE[mt][2 * j2 + 1], a0[mt], bf[4 * j2 + 1], bf[4 * j2 + 3]);
                    }
            }
            {   // kx=2 -> odd sites (cell m part)
                uint32_t bf[8];
                ldsm4(bf,     W2 + bB0 + ob);
                ldsm4(bf + 4, W2 + bB1 + ob);
#pragma unroll
                for (int j2 = 0; j2 < 2; j2++)
#pragma unroll
                    for (int mt = 0; mt < 2; mt++) {
                        mma_tf32(accO[mt][2 * j2],     a0[mt], bf[4 * j2],     bf[4 * j2 + 2]);
                        mma_tf32(accO[mt][2 * j2 + 1], a0[mt], bf[4 * j2 + 1], bf[4 * j2 + 3]);
                    }
            }
            {   // kx=0 -> accP over OWN rows; epilogue shifts rows by +1
                uint32_t bf[8];
                ldsm4(bf,     W0 + bB0 + ob);
                ldsm4(bf + 4, W0 + bB1 + ob);
#pragma unroll
                for (int j2 = 0; j2 < 2; j2++)
#pragma unroll
                    for (int mt = 0; mt < 2; mt++) {
                        mma_tf32(accP[mt][2 * j2],     a0[mt], bf[4 * j2],     bf[4 * j2 + 2]);
                        mma_tf32(accP[mt][2 * j2 + 1], a0[mt], bf[4 * j2 + 1], bf[4 * j2 + 3]);
                    }
            }
        }
        __syncwarp();
        if (lane == 0) MBARRIER_ARRIVE(buf ? mbE1 : mbE0);
        if (tid == 0 && st + 2 < nStage) {
            if (buf) { MBARRIER_WAIT_PARITY(mbE1, phE1); phE1 ^= 1; }
            else     { MBARRIER_WAIT_PARITY(mbE0, phE0); phE0 ^= 1; }
            FETCH(st + 2, S, buf ? mbF1 : mbF0);
        }
    }
#undef FETCH

    // ---------------- epilogue: row-shift accP, stores + stats ----------------
    const unsigned FULL = 0xffffffffu;
    const int g = lane >> 2;
    const int lc = lane & 3;
    const int n0base = lc * 2;
    const int sbase = ((b * TQ + ot) * YOQ + oy) * XOQ;
    const bool g7 = (g == 7);

    // stage boundary row (each warp's row r0, cols of its half) for warp wid-2
    if (lane < 4) {
#pragma unroll
        for (int nt = 0; nt < 4; nt++) {
            stageP[wid][nt * 8 + lane * 2 + 0] = accP[0][nt][0];
            stageP[wid][nt * 8 + lane * 2 + 1] = accP[0][nt][1];
        }
    }
    __syncthreads();

    float sl[8] = {0,0,0,0,0,0,0,0}, ql[8] = {0,0,0,0,0,0,0,0};
#pragma unroll
    for (int mt = 0; mt < 2; mt++) {
        const int mA = r0 + 16 * mt + g;
        const int mB = mA + 8;
        const bool oddBvalid = (mB != 127);      // odd site 255 doesn't exist
#pragma unroll
        for (int nt = 0; nt < 4; nt++) {
            // shifted accP: rows +1
            float pdn0 = __shfl_down_sync(FULL, accP[mt][nt][0], 4);
            float pdn1 = __shfl_down_sync(FULL, accP[mt][nt][1], 4);
            float pw0  = __shfl_sync(FULL, accP[mt][nt][2], lc);
            float pw1  = __shfl_sync(FULL, accP[mt][nt][3], lc);
            float p0 = g7 ? pw0 : pdn0;
            float p1 = g7 ? pw1 : pdn1;
            float pdn2 = __shfl_down_sync(FULL, accP[mt][nt][2], 4);
            float pdn3 = __shfl_down_sync(FULL, accP[mt][nt][3], 4);
            float pb2, pb3;
            if (mt == 0) {
                pb2 = __shfl_sync(FULL, accP[1][nt][0], lc);
                pb3 = __shfl_sync(FULL, accP[1][nt][1], lc);
            } else {
                pb2 = (wm < 3) ? stageP[wid + 2][nt * 8 + lc * 2 + 0] : 0.f;
                pb3 = (wm < 3) ? stageP[wid + 2][nt * 8 + lc * 2 + 1] : 0.f;
            }
            float p2 = g7 ? pb2 : pdn2;
            float p3 = g7 ? pb3 : pdn3;
            float o0 = accO[mt][nt][0] + p0;
            float o1 = accO[mt][nt][1] + p1;
            float o2 = accO[mt][nt][2] + p2;
            float o3 = accO[mt][nt][3] + p3;

            int n0 = half * 32 + nt * 8 + n0base;
            *(float2*)(out + (size_t)(sbase + 2 * mA) * COUTQ + n0) =
                make_float2(accE[mt][nt][0], accE[mt][nt][1]);
            *(float2*)(out + (size_t)(sbase + 2 * mB) * COUTQ + n0) =
                make_float2(accE[mt][nt][2], accE[mt][nt][3]);
            *(float2*)(out + (size_t)(sbase + 2 * mA + 1) * COUTQ + n0) =
                make_float2(o0, o1);
            if (oddBvalid)
                *(float2*)(out + (size_t)(sbase + 2 * mB + 1) * COUTQ + n0) =
                    make_float2(o2, o3);
#pragma unroll
            for (int c = 0; c < 2; c++) {
                float e0 = accE[mt][nt][c], e2 = accE[mt][nt][2 + c];
                float q0 = (c == 0) ? o0 : o1;
                float q2 = oddBvalid ? ((c == 0) ? o2 : o3) : 0.f;
                sl[nt * 2 + c] += e0 + e2 + q0 + q2;
                ql[nt * 2 + c] += e0 * e0 + e2 * e2 + q0 * q0 + q2 * q2;
            }
        }
    }
#pragma unroll
    for (int d = 4; d <= 16; d <<= 1) {
#pragma unroll
        for (int i = 0; i < 8; i++) {
            sl[i] += __shfl_xor_sync(FULL, sl[i], d);
            ql[i] += __shfl_xor_sync(FULL, ql[i], d);
        }
    }
    __syncthreads();                          // stage reads done; reuse smem
    float* redS = (float*)smem;               // [8 warps][4][8]
    float* redQ = (float*)(smem + 8 * 4 * 8 * 4);
    if (lane < 4) {
#pragma unroll
        for (int i = 0; i < 8; i++) {
            redS[(wid * 4 + lane) * 8 + i] = sl[i];
            redQ[(wid * 4 + lane) * 8 + i] = ql[i];
        }
    }
    __syncthreads();
    if (tid < COUTQ) {
        int h2 = tid >> 5, nt = (tid >> 3) & 3, c4 = (tid >> 1) & 3, cc = tid & 1;
        int idx = nt * 2 + cc;
        float S = 0.f, Q = 0.f;
#pragma unroll
        for (int wmx = 0; wmx < 4; wmx++) {
            int w = wmx * 2 + h2;
            S += redS[(w * 4 + c4) * 8 + idx];
            Q += redQ[(w * 4 + c4) * 8 + idx];
        }
        atomicAdd(&g_sum[tid], S);
        atomicAdd(&g_sumsq[tid], Q);
    }

    // ---------------- active-site mask ----------------
    bool act = false;
    if (tid < XOQ) {
        int ox2 = tid;
        int xc[2]; int nxc = 0;
        if ((ox2 & 1) == 0) { xc[nxc++] = ox2 >> 1; }
        else {
            int c0 = (ox2 + 1) >> 1;
            if (c0 < XQ) xc[nxc++] = c0;
            xc[nxc++] = (ox2 - 1) >> 1;
        }
        for (int kt = 0; kt < 3 && !act; kt++) {
            int ctv = ot + 1 - kt;
            if (ctv < 0 || ctv >= TQ) continue;
            for (int yt = 0; yt < nky && !act; yt++) {
                int cb2 = ((b * TQ + ctv) * YQ + cys[yt]) * XQ;
                for (int xi = 0; xi < nxc; xi++)
                    if (g_occ[cb2 + xc[xi]] > 0) { act = true; break; }
            }
        }
        g_mask[sbase + ox2] = act ? 1 : 0;
    }
    unsigned bal = __ballot_sync(FULL, act);
    if (lane == 0 && bal) atomicAdd(&g_nactive, __popc(bal));
}

// ---------------- K3: fold BN params ----------------
__global__ void k_bn(const float* __restrict__ gamma, const float* __restrict__ beta) {
    int c = threadIdx.x;
    if (c >= COUTQ) return;
    float n = (float)max(g_nactive, 1);
    float mean = g_sum[c] / n;
    float var  = g_sumsq[c] / n - mean * mean;
    float rstd = rsqrtf(var + EPSQ);
    float sc   = rstd * gamma[c];
    g_scale[c] = sc;
    g_shift[c] = beta[c] - mean * sc;
}

// ---------------- K4: normalize + relu + mask (in place; mask-gated read) ----------------
__global__ void k_final(float* __restrict__ out) {
    int i = blockIdx.x * 256 + threadIdx.x;
    int site = i >> 4;
    int cg   = i & 15;
    float4 v;
    if (g_mask[site]) {
        v = ((float4*)out)[i];
        float4 sc = ((const float4*)g_scale)[cg];
        float4 sh = ((const float4*)g_shift)[cg];
        v.x = fmaxf(v.x * sc.x + sh.x, 0.f);
        v.y = fmaxf(v.y * sc.y + sh.y, 0.f);
        v.z = fmaxf(v.z * sc.z + sh.z, 0.f);
        v.w = fmaxf(v.w * sc.w + sh.w, 0.f);
    } else {
        v = make_float4(0.f, 0.f, 0.f, 0.f);
    }
    ((float4*)out)[i] = v;
}

// ---------------- launch ----------------
extern "C" void kernel_launch(void* const* d_in, const int* in_sizes, int n_in,
                              void* d_out, int out_size) {
    const float* feats  = (const float*)d_in[0];
    const float* weight = (const float*)d_in[1];
    const float* gamma  = (const float*)d_in[2];
    const float* beta   = (const float*)d_in[3];
    const int*   cb     = (const int*)d_in[4];
    const int*   ct     = (const int*)d_in[5];
    const int*   cy     = (const int*)d_in[6];
    const int*   cx     = (const int*)d_in[7];
    float* out = (float*)d_out;

    cudaFuncSetAttribute(k_conv, cudaFuncAttributeMaxDynamicSharedMemorySize, CONV_DYN_SMEM);

    k_zero<<<NCELL * CIN / 4 / 256, 256>>>(weight);
    k_scatter<<<NPTS * 32 / 256, 256>>>(feats, cb, ct, cy, cx);
    k_conv<<<BQ * TQ * YOQ, 256, CONV_DYN_SMEM>>>(out);
    k_bn<<<1, 64>>>(gamma, beta);
    k_final<<<NSITE * 16 / 256, 256>>>(out);
}

// round 16
// speedup vs baseline: 1.0142x; 1.0142x over previous
#include <cuda_runtime.h>
#include <cuda_bf16.h>
#include <cstdint>

// ---------------- problem constants ----------------
#define BQ 2
#define TQ 8
#define YQ 128
#define XQ 128
#define CIN 128
#define COUTQ 64
#define YOQ 255
#define XOQ 255
#define NPTS 262144
#define NCELL (BQ*TQ*YQ*XQ)
#define NSITE (BQ*TQ*YOQ*XOQ)
#define NSLAB (BQ*TQ*YQ)
#define EPSQ 1e-5f

// ---------------- device scratch ----------------
// fp32 cell features stored DIRECTLY in the swizzled quarter-image layout:
// [slab][kq 0..3][cell*128 + swz8(c8, cell&7)] (16KB per quarter, 64KB per slab)
__device__ __align__(16) float g_Ab[(size_t)NSLAB * 16384];
__device__ __align__(16) int   g_occ[NCELL];
__device__ unsigned char       g_mask[NSITE];
__device__ __align__(16) float g_sum[COUTQ];
__device__ __align__(16) float g_sumsq[COUTQ];
__device__ int                 g_nactive;
// pre-swizzled tf32 W images: [ktky 0..8][kq 0..3][kx 0..2][co*128 + swz8] (24KB per (ktky,kq))
__device__ __align__(16) unsigned char g_Wt[9 * 4 * 3 * 8192];

// ---------------- helpers ----------------
__device__ __forceinline__ uint32_t smem_u32(const void* p) {
    uint32_t a;
    asm("{ .reg .u64 t; cvta.to.shared.u64 t, %1; cvt.u32.u64 %0, t; }" : "=r"(a) : "l"(p));
    return a;
}
__device__ __forceinline__ void ldsm4(uint32_t* r, uint32_t addr) {
    asm volatile("ldmatrix.sync.aligned.m8n8.x4.shared.b16 {%0,%1,%2,%3}, [%4];"
        : "=r"(r[0]), "=r"(r[1]), "=r"(r[2]), "=r"(r[3]) : "r"(addr));
}
__device__ __forceinline__ void mma_tf32(float* c, const uint32_t* a, uint32_t b0, uint32_t b1) {
    asm volatile("mma.sync.aligned.m16n8k8.row.col.f32.tf32.tf32.f32 "
        "{%0,%1,%2,%3}, {%4,%5,%6,%7}, {%8,%9}, {%0,%1,%2,%3};"
        : "+f"(c[0]), "+f"(c[1]), "+f"(c[2]), "+f"(c[3])
        : "r"(a[0]), "r"(a[1]), "r"(a[2]), "r"(a[3]), "r"(b0), "r"(b1));
}
__device__ __forceinline__ uint32_t f2tf32(float x) {
    uint32_t t;
    asm("cvt.rna.tf32.f32 %0, %1;" : "=r"(t) : "f"(x));
    return t;
}
__device__ __forceinline__ void bulkcp(uint32_t dst, const void* src, uint32_t bytes, uint32_t mbar) {
    asm volatile("cp.async.bulk.shared::cluster.global.mbarrier::complete_tx::bytes "
                 "[%0], [%1], %2, [%3];"
                 :: "r"(dst), "l"(src), "r"(bytes), "r"(mbar) : "memory");
}
#define MBARRIER_INIT(addr, cnt) \
    asm volatile("mbarrier.init.shared.b64 [%0], %1;" :: "r"((uint32_t)(addr)), "r"((uint32_t)(cnt)) : "memory")
#define MBARRIER_EXPECT_TX(addr, tx) \
    asm volatile("mbarrier.arrive.expect_tx.shared.b64 _, [%0], %1;" \
        :: "r"((uint32_t)(addr)), "r"((uint32_t)(tx)) : "memory")
#define MBARRIER_ARRIVE(addr) \
    asm volatile("mbarrier.arrive.shared.b64 _, [%0];" :: "r"((uint32_t)(addr)) : "memory")
#define MBARRIER_WAIT_PARITY(addr, par) do { \
    uint32_t _m = (uint32_t)(addr); uint32_t _p = (uint32_t)(par); uint32_t _d; \
    asm volatile("{\n\t.reg .pred p;\n\tmbarrier.try_wait.parity.acquire.cta.shared::cta.b64 p, [%1], %2;\n\tselp.b32 %0, 1, 0, p;\n\t}" \
        : "=r"(_d) : "r"(_m), "r"(_p) : "memory"); \
    if (!_d) { \
        asm volatile("{\n\t.reg .pred P1;\n\tWL_%=:\n\tmbarrier.try_wait.parity.acquire.cta.shared::cta.b64 P1, [%0], %1, 0x989680;\n\t@P1 bra.uni WD_%=;\n\tbra.uni WL_%=;\n\tWD_%=:\n\t}" \
            :: "r"(_m), "r"(_p) : "memory"); \
    } } while (0)

// 128B rows of 8 16B-chunks, XOR-swizzled.
__device__ __forceinline__ uint32_t swz8(int c8, int rs) {
    return (uint32_t)(((c8 ^ rs) & 7) << 4);
}

// ---------------- K0: zero scratch (g_Ab in image layout) + prep W images ----------------
__global__ void k_zero(const float* __restrict__ W) {
    int idx = blockIdx.x * 256 + threadIdx.x;
    if (idx < NCELL * CIN / 4)
        ((float4*)g_Ab)[idx] = make_float4(0.f, 0.f, 0.f, 0.f);
    if (idx < NCELL / 4)
        ((int4*)g_occ)[idx] = make_int4(0, 0, 0, 0);
    if (idx < COUTQ) { g_sum[idx] = 0.f; g_sumsq[idx] = 0.f; }
    if (idx == 0) g_nactive = 0;
    if (idx < 27 * COUTQ * 32) {
        int koff = idx >> 11;
        int r    = idx & 2047;
        int co = r >> 5, c32 = r & 31;
        int kq = c32 >> 3, c8 = c32 & 7;
        int ktky = koff / 3, kx = koff % 3;
        uint32_t v[4];
#pragma unroll
        for (int j = 0; j < 4; j++) {
            int ci = c32 * 4 + j;
            v[j] = f2tf32(W[((size_t)koff * CIN + ci) * COUTQ + co]);
        }
        uint32_t dst = (uint32_t)(((ktky * 4 + kq) * 3 + kx) * 8192)
                     + (uint32_t)(co * 128) + swz8(c8, co & 7);
        *(uint4*)(g_Wt + dst) = make_uint4(v[0], v[1], v[2], v[3]);
    }
}

// ---------------- K1: scatter points directly into swizzled image ----------------
__global__ void k_scatter(const float* __restrict__ feats,
                          const int* __restrict__ cb, const int* __restrict__ ct,
                          const int* __restrict__ cy, const int* __restrict__ cx) {
    int i = blockIdx.x * 256 + threadIdx.x;
    if (i >= NPTS * 32) return;
    int p  = i >> 5;
    int c4 = i & 31;
    int slab = (cb[p] * TQ + ct[p]) * YQ + cy[p];
    int cell = cx[p];
    float4 v = ((const float4*)feats)[p * 32 + c4];
    int kq = c4 >> 3, c8 = c4 & 7;
    float* dst = g_Ab + (size_t)slab * 16384 + kq * 4096
               + cell * 32 + (swz8(c8, cell & 7) >> 2);
    atomicAdd(dst + 0, v.x);
    atomicAdd(dst + 1, v.y);
    atomicAdd(dst + 2, v.z);
    atomicAdd(dst + 3, v.w);
    if (c4 == 0) atomicAdd(&g_occ[slab * XQ + cell], 1);
}

// ---------------- K2: occ-2, quarter-stage bulk-copy tf32 conv (R14 structure) ----------------
// Stage (40KB): A-quarter [0,16K), W [16K,40K) (kx stride 8K). 2 buffers.
#define STG 40960
#define CONV_DYN_SMEM (2 * STG)

__global__ void __launch_bounds__(256, 2) k_conv(float* __restrict__ out) {
    extern __shared__ char smem[];
    __shared__ __align__(8) uint64_t mb[4];   // full0, full1, empty0, empty1
    const uint32_t sb = smem_u32(smem);
    const uint32_t mbF0 = smem_u32(&mb[0]), mbF1 = smem_u32(&mb[1]);
    const uint32_t mbE0 = smem_u32(&mb[2]), mbE1 = smem_u32(&mb[3]);
    const int tid = threadIdx.x, wid = tid >> 5, lane = tid & 31;
    const int half = wid & 1, wm = wid >> 1;

    const int bid = blockIdx.x;
    const int oy = bid % YOQ;
    const int bt = bid / YOQ;
    const int b = bt >> 3, ot = bt & 7;

    // y taps
    int nky, cys[2], kys[2];
    if ((oy & 1) == 0) { nky = 1; cys[0] = oy >> 1;       kys[0] = 1; }
    else               { nky = 2; cys[0] = (oy + 1) >> 1; kys[0] = 0;
                                  cys[1] = (oy - 1) >> 1; kys[1] = 2; }

    // iteration list
    int nIter = 0, slabI[6], ktkyI[6];
    for (int kt = 0; kt < 3; kt++) {
        int ctv = ot + 1 - kt;
        if (ctv < 0 || ctv >= TQ) continue;
        for (int yt = 0; yt < nky; yt++) {
            slabI[nIter] = (b * TQ + ctv) * YQ + cys[yt];
            ktkyI[nIter] = kt * 3 + kys[yt];
            nIter++;
        }
    }
    const int nStage = nIter * 4;

    if (tid == 0) {
        MBARRIER_INIT(mbF0, 1); MBARRIER_INIT(mbF1, 1);
        MBARRIER_INIT(mbE0, 8); MBARRIER_INIT(mbE1, 8);
    }
    __syncthreads();

    // ldmatrix geometry (128B rows)
    const int r0 = wm << 5;
    const int matL = lane >> 3, rr = lane & 7;
    const int cSel = matL >> 1;
    int rowA0[2];
    rowA0[0] = r0 + rr + ((matL & 1) << 3);
    rowA0[1] = rowA0[0] + 16;
    const uint32_t bA0[2] = { (uint32_t)rowA0[0] * 128, (uint32_t)rowA0[1] * 128 };
    const uint32_t bA1[2] = { bA0[0] + 128, bA0[1] + 128 };   // rows +1 (row 128 garbage, masked)
    const int rs0[2] = { rowA0[0] & 7, rowA0[1] & 7 };
    const int rs1[2] = { (rowA0[0] + 1) & 7, (rowA0[1] + 1) & 7 };
    const int rowB = half * 32 + rr + ((matL & 1) << 3);
    const uint32_t bB0 = (uint32_t)rowB * 128;
    const uint32_t bB1 = bB0 + 16 * 128;
    const int rsB = rowB & 7;

    float accE[2][4][4], accO[2][4][4];
#pragma unroll
    for (int mt = 0; mt < 2; mt++)
#pragma unroll
        for (int i = 0; i < 4; i++)
#pragma unroll
            for (int j = 0; j < 4; j++) { accE[mt][i][j] = 0.f; accO[mt][i][j] = 0.f; }

#define FETCH(ST, DST, MBAR) do { \
    int _it = (ST) >> 2, _kq = (ST) & 3; \
    MBARRIER_EXPECT_TX(MBAR, STG); \
    bulkcp((DST),         (const char*)g_Ab + (size_t)slabI[_it] * 65536 + _kq * 16384, 16384, MBAR); \
    bulkcp((DST) + 16384, g_Wt + (size_t)(ktkyI[_it] * 4 + _kq) * 24576,   24576, MBAR); \
} while (0)

    if (tid == 0) {
        FETCH(0, sb, mbF0);
        FETCH(1, sb + STG, mbF1);
    }

    int phF0 = 0, phF1 = 0, phE0 = 0, phE1 = 0;
    for (int st = 0; st < nStage; st++) {
        const int buf = st & 1;
        const uint32_t S = sb + (uint32_t)buf * STG;
        if (buf) { MBARRIER_WAIT_PARITY(mbF1, phF1); phF1 ^= 1; }
        else     { MBARRIER_WAIT_PARITY(mbF0, phF0); phF0 ^= 1; }

        const uint32_t W0 = S + 16384;            // kx=0
        const uint32_t W1 = S + 16384 + 8192;     // kx=1
        const uint32_t W2 = S + 16384 + 16384;    // kx=2
#pragma unroll
        for (int s = 0; s < 4; s++) {
            int ck = 2 * s + cSel;
            uint32_t a0[2][4], a1[2][4];
            uint32_t b1f[8], b2f[8], b0f[8];
#pragma unroll
            for (int mt = 0; mt < 2; mt++) {
                ldsm4(a0[mt], S + bA0[mt] + swz8(ck, rs0[mt]));
                ldsm4(a1[mt], S + bA1[mt] + swz8(ck, rs1[mt]));
            }
            {
                uint32_t ob = swz8(ck, rsB);
                ldsm4(b1f,     W1 + bB0 + ob);
                ldsm4(b1f + 4, W1 + bB1 + ob);
                ldsm4(b2f,     W2 + bB0 + ob);
                ldsm4(b2f + 4, W2 + bB1 + ob);
                ldsm4(b0f,     W0 + bB0 + ob);
                ldsm4(b0f + 4, W0 + bB1 + ob);
            }
#pragma unroll
            for (int j2 = 0; j2 < 2; j2++)
#pragma unroll
                for (int mt = 0; mt < 2; mt++) {
                    mma_tf32(accE[mt][2 * j2],     a0[mt], b1f[4 * j2],     b1f[4 * j2 + 2]);
                    mma_tf32(accE[mt][2 * j2 + 1], a0[mt], b1f[4 * j2 + 1], b1f[4 * j2 + 3]);
                }
#pragma unroll
            for (int j2 = 0; j2 < 2; j2++)
#pragma unroll
                for (int mt = 0; mt < 2; mt++) {
                    mma_tf32(accO[mt][2 * j2],     a0[mt], b2f[4 * j2],     b2f[4 * j2 + 2]);
                    mma_tf32(accO[mt][2 * j2 + 1], a0[mt], b2f[4 * j2 + 1], b2f[4 * j2 + 3]);
                }
#pragma unroll
            for (int j2 = 0; j2 < 2; j2++)
#pragma unroll
                for (int mt = 0; mt < 2; mt++) {
                    mma_tf32(accO[mt][2 * j2],     a1[mt], b0f[4 * j2],     b0f[4 * j2 + 2]);
                    mma_tf32(accO[mt][2 * j2 + 1], a1[mt], b0f[4 * j2 + 1], b0f[4 * j2 + 3]);
                }
        }
        __syncwarp();
        if (lane == 0) MBARRIER_ARRIVE(buf ? mbE1 : mbE0);
        if (tid == 0 && st + 2 < nStage) {
            if (buf) { MBARRIER_WAIT_PARITY(mbE1, phE1); phE1 ^= 1; }
            else     { MBARRIER_WAIT_PARITY(mbE0, phE0); phE0 ^= 1; }
            FETCH(st + 2, S, buf ? mbF1 : mbF0);
        }
    }
#undef FETCH

    // ---------------- epilogue: stores + stats ----------------
    const int g = lane >> 2;
    const int n0base = (lane & 3) * 2;
    const int sbase = ((b * TQ + ot) * YOQ + oy) * XOQ;

    float sl[8] = {0,0,0,0,0,0,0,0}, ql[8] = {0,0,0,0,0,0,0,0};
#pragma unroll
    for (int mt = 0; mt < 2; mt++) {
        const int mA = r0 + 16 * mt + g;
        const int mB = mA + 8;
        const bool oddBvalid = (mB != 127);      // ox=255 doesn't exist
#pragma unroll
        for (int nt = 0; nt < 4; nt++) {
            int n0 = half * 32 + nt * 8 + n0base;
            *(float2*)(out + (size_t)(sbase + 2 * mA) * COUTQ + n0) =
                make_float2(accE[mt][nt][0], accE[mt][nt][1]);
            *(float2*)(out + (size_t)(sbase + 2 * mB) * COUTQ + n0) =
                make_float2(accE[mt][nt][2], accE[mt][nt][3]);
            *(float2*)(out + (size_t)(sbase + 2 * mA + 1) * COUTQ + n0) =
                make_float2(accO[mt][nt][0], accO[mt][nt][1]);
            if (oddBvalid)
                *(float2*)(out + (size_t)(sbase + 2 * mB + 1) * COUTQ + n0) =
                    make_float2(accO[mt][nt][2], accO[mt][nt][3]);
#pragma unroll
            for (int c = 0; c < 2; c++) {
                float e0 = accE[mt][nt][c], e2 = accE[mt][nt][2 + c];
                float o0 = accO[mt][nt][c], o2 = oddBvalid ? accO[mt][nt][2 + c] : 0.f;
                sl[nt * 2 + c] += e0 + e2 + o0 + o2;
                ql[nt * 2 + c] += e0 * e0 + e2 * e2 + o0 * o0 + o2 * o2;
            }
        }
    }
#pragma unroll
    for (int d = 4; d <= 16; d <<= 1) {
#pragma unroll
        for (int i = 0; i < 8; i++) {
            sl[i] += __shfl_xor_sync(0xffffffffu, sl[i], d);
            ql[i] += __shfl_xor_sync(0xffffffffu, ql[i], d);
        }
    }
    __syncthreads();                          // pipeline drained; reuse smem
    float* redS = (float*)smem;               // [8 warps][4][8]
    float* redQ = (float*)(smem + 8 * 4 * 8 * 4);
    if (lane < 4) {
#pragma unroll
        for (int i = 0; i < 8; i++) {
            redS[(wid * 4 + lane) * 8 + i] = sl[i];
            redQ[(wid * 4 + lane) * 8 + i] = ql[i];
        }
    }
    __syncthreads();
    if (tid < COUTQ) {
        int h2 = tid >> 5, nt = (tid >> 3) & 3, c4 = (tid >> 1) & 3, cc = tid & 1;
        int idx = nt * 2 + cc;
        float S = 0.f, Q = 0.f;
#pragma unroll
        for (int wmx = 0; wmx < 4; wmx++) {
            int w = wmx * 2 + h2;
            S += redS[(w * 4 + c4) * 8 + idx];
            Q += redQ[(w * 4 + c4) * 8 + idx];
        }
        atomicAdd(&g_sum[tid], S);
        atomicAdd(&g_sumsq[tid], Q);
    }

    // ---------------- active-site mask ----------------
    bool act = false;
    if (tid < XOQ) {
        int ox2 = tid;
        int xc[2]; int nxc = 0;
        if ((ox2 & 1) == 0) { xc[nxc++] = ox2 >> 1; }
        else {
            int c0 = (ox2 + 1) >> 1;
            if (c0 < XQ) xc[nxc++] = c0;
            xc[nxc++] = (ox2 - 1) >> 1;
        }
        for (int kt = 0; kt < 3 && !act; kt++) {
            int ctv = ot + 1 - kt;
            if (ctv < 0 || ctv >= TQ) continue;
            for (int yt = 0; yt < nky && !act; yt++) {
                int cb2 = ((b * TQ + ctv) * YQ + cys[yt]) * XQ;
                for (int xi = 0; xi < nxc; xi++)
                    if (g_occ[cb2 + xc[xi]] > 0) { act = true; break; }
            }
        }
        g_mask[sbase + ox2] = act ? 1 : 0;
    }
    unsigned bal = __ballot_sync(0xffffffffu, act);
    if (lane == 0 && bal) atomicAdd(&g_nactive, __popc(bal));
}

// ---------------- K3: normalize + relu + mask (BN fold done in-block) ----------------
__global__ void k_final(float* __restrict__ out,
                        const float* __restrict__ gamma, const float* __restrict__ beta) {
    __shared__ float s_scale[COUTQ], s_shift[COUTQ];
    int tid = threadIdx.x;
    if (tid < COUTQ) {
        float n = (float)max(g_nactive, 1);
        float mean = g_sum[tid] / n;
        float var  = g_sumsq[tid] / n - mean * mean;
        float rstd = rsqrtf(var + EPSQ);
        float sc   = rstd * gamma[tid];
        s_scale[tid] = sc;
        s_shift[tid] = beta[tid] - mean * sc;
    }
    __syncthreads();
    int i = blockIdx.x * 256 + tid;
    int site = i >> 4;
    int cg   = i & 15;
    float4 v  = ((float4*)out)[i];
    float4 sc = *(const float4*)(s_scale + cg * 4);
    float4 sh = *(const float4*)(s_shift + cg * 4);
    float  m  = g_mask[site] ? 1.f : 0.f;
    v.x = fmaxf(v.x * sc.x + sh.x, 0.f) * m;
    v.y = fmaxf(v.y * sc.y + sh.y, 0.f) * m;
    v.z = fmaxf(v.z * sc.z + sh.z, 0.f) * m;
    v.w = fmaxf(v.w * sc.w + sh.w, 0.f) * m;
    ((float4*)out)[i] = v;
}

// ---------------- launch ----------------
extern "C" void kernel_launch(void* const* d_in, const int* in_sizes, int n_in,
                              void* d_out, int out_size) {
    const float* feats  = (const float*)d_in[0];
    const float* weight = (const float*)d_in[1];
    const float* gamma  = (const float*)d_in[2];
    const float* beta   = (const float*)d_in[3];
    const int*   cb     = (const int*)d_in[4];
    const int*   ct     = (const int*)d_in[5];
    const int*   cy     = (const int*)d_in[6];
    const int*   cx     = (const int*)d_in[7];
    float* out = (float*)d_out;

    cudaFuncSetAttribute(k_conv, cudaFuncAttributeMaxDynamicSharedMemorySize, CONV_DYN_SMEM);

    k_zero<<<NCELL * CIN / 4 / 256, 256>>>(weight);
    k_scatter<<<NPTS * 32 / 256, 256>>>(feats, cb, ct, cy, cx);
    k_conv<<<BQ * TQ * YOQ, 256, CONV_DYN_SMEM>>>(out);
    k_final<<<NSITE * 16 / 256, 256>>>(out, gamma, beta);
}

// round 17
// speedup vs baseline: 1.0264x; 1.0120x over previous
#include <cuda_runtime.h>
#include <cuda_bf16.h>
#include <cstdint>

// ---------------- problem constants ----------------
#define BQ 2
#define TQ 8
#define YQ 128
#define XQ 128
#define CIN 128
#define COUTQ 64
#define YOQ 255
#define XOQ 255
#define NPTS 262144
#define NCELL (BQ*TQ*YQ*XQ)
#define NSITE (BQ*TQ*YOQ*XOQ)
#define NSLAB (BQ*TQ*YQ)
#define EPSQ 1e-5f

// ---------------- device scratch ----------------
// fp32 cell features stored DIRECTLY in the swizzled quarter-image layout:
// [slab][kq 0..3][cell*128 + swz8(c8, cell&7)] (16KB per quarter, 64KB per slab)
__device__ __align__(16) float g_Ab[(size_t)NSLAB * 16384];
__device__ __align__(16) int   g_occ[NCELL];
__device__ unsigned char       g_mask[NSITE];
__device__ __align__(16) float g_sum[COUTQ];
__device__ __align__(16) float g_sumsq[COUTQ];
__device__ int                 g_nactive;
// pre-swizzled tf32 W images: [ktky 0..8][kq 0..3][kx 0..2][co*128 + swz8] (24KB per (ktky,kq))
__device__ __align__(16) unsigned char g_Wt[9 * 4 * 3 * 8192];

// ---------------- helpers ----------------
__device__ __forceinline__ uint32_t smem_u32(const void* p) {
    uint32_t a;
    asm("{ .reg .u64 t; cvta.to.shared.u64 t, %1; cvt.u32.u64 %0, t; }" : "=r"(a) : "l"(p));
    return a;
}
__device__ __forceinline__ void ldsm4(uint32_t* r, uint32_t addr) {
    asm volatile("ldmatrix.sync.aligned.m8n8.x4.shared.b16 {%0,%1,%2,%3}, [%4];"
        : "=r"(r[0]), "=r"(r[1]), "=r"(r[2]), "=r"(r[3]) : "r"(addr));
}
__device__ __forceinline__ void mma_tf32(float* c, const uint32_t* a, uint32_t b0, uint32_t b1) {
    asm volatile("mma.sync.aligned.m16n8k8.row.col.f32.tf32.tf32.f32 "
        "{%0,%1,%2,%3}, {%4,%5,%6,%7}, {%8,%9}, {%0,%1,%2,%3};"
        : "+f"(c[0]), "+f"(c[1]), "+f"(c[2]), "+f"(c[3])
        : "r"(a[0]), "r"(a[1]), "r"(a[2]), "r"(a[3]), "r"(b0), "r"(b1));
}
__device__ __forceinline__ uint32_t f2tf32(float x) {
    uint32_t t;
    asm("cvt.rna.tf32.f32 %0, %1;" : "=r"(t) : "f"(x));
    return t;
}
__device__ __forceinline__ void bulkcp(uint32_t dst, const void* src, uint32_t bytes, uint32_t mbar) {
    asm volatile("cp.async.bulk.shared::cluster.global.mbarrier::complete_tx::bytes "
                 "[%0], [%1], %2, [%3];"
                 :: "r"(dst), "l"(src), "r"(bytes), "r"(mbar) : "memory");
}
#define MBARRIER_INIT(addr, cnt) \
    asm volatile("mbarrier.init.shared.b64 [%0], %1;" :: "r"((uint32_t)(addr)), "r"((uint32_t)(cnt)) : "memory")
#define MBARRIER_EXPECT_TX(addr, tx) \
    asm volatile("mbarrier.arrive.expect_tx.shared.b64 _, [%0], %1;" \
        :: "r"((uint32_t)(addr)), "r"((uint32_t)(tx)) : "memory")
#define MBARRIER_ARRIVE(addr) \
    asm volatile("mbarrier.arrive.shared.b64 _, [%0];" :: "r"((uint32_t)(addr)) : "memory")
#define MBARRIER_WAIT_PARITY(addr, par) do { \
    uint32_t _m = (uint32_t)(addr); uint32_t _p = (uint32_t)(par); uint32_t _d; \
    asm volatile("{\n\t.reg .pred p;\n\tmbarrier.try_wait.parity.acquire.cta.shared::cta.b64 p, [%1], %2;\n\tselp.b32 %0, 1, 0, p;\n\t}" \
        : "=r"(_d) : "r"(_m), "r"(_p) : "memory"); \
    if (!_d) { \
        asm volatile("{\n\t.reg .pred P1;\n\tWL_%=:\n\tmbarrier.try_wait.parity.acquire.cta.shared::cta.b64 P1, [%0], %1, 0x989680;\n\t@P1 bra.uni WD_%=;\n\tbra.uni WL_%=;\n\tWD_%=:\n\t}" \
            :: "r"(_m), "r"(_p) : "memory"); \
    } } while (0)

// 128B rows of 8 16B-chunks, XOR-swizzled.
__device__ __forceinline__ uint32_t swz8(int c8, int rs) {
    return (uint32_t)(((c8 ^ rs) & 7) << 4);
}

// ---------------- K0: zero scratch (g_Ab in image layout) + prep W images ----------------
__global__ void k_zero(const float* __restrict__ W) {
    int idx = blockIdx.x * 256 + threadIdx.x;
    if (idx < NCELL * CIN / 4)
        ((float4*)g_Ab)[idx] = make_float4(0.f, 0.f, 0.f, 0.f);
    if (idx < NCELL / 4)
        ((int4*)g_occ)[idx] = make_int4(0, 0, 0, 0);
    if (idx < COUTQ) { g_sum[idx] = 0.f; g_sumsq[idx] = 0.f; }
    if (idx == 0) g_nactive = 0;
    if (idx < 27 * COUTQ * 32) {
        int koff = idx >> 11;
        int r    = idx & 2047;
        int co = r >> 5, c32 = r & 31;
        int kq = c32 >> 3, c8 = c32 & 7;
        int ktky = koff / 3, kx = koff % 3;
        uint32_t v[4];
#pragma unroll
        for (int j = 0; j < 4; j++) {
            int ci = c32 * 4 + j;
            v[j] = f2tf32(W[((size_t)koff * CIN + ci) * COUTQ + co]);
        }
        uint32_t dst = (uint32_t)(((ktky * 4 + kq) * 3 + kx) * 8192)
                     + (uint32_t)(co * 128) + swz8(c8, co & 7);
        *(uint4*)(g_Wt + dst) = make_uint4(v[0], v[1], v[2], v[3]);
    }
}

// ---------------- K1: scatter points directly into swizzled image ----------------
__global__ void k_scatter(const float* __restrict__ feats,
                          const int* __restrict__ cb, const int* __restrict__ ct,
                          const int* __restrict__ cy, const int* __restrict__ cx) {
    int i = blockIdx.x * 256 + threadIdx.x;
    if (i >= NPTS * 32) return;
    int p  = i >> 5;
    int c4 = i & 31;
    int slab = (cb[p] * TQ + ct[p]) * YQ + cy[p];
    int cell = cx[p];
    float4 v = ((const float4*)feats)[p * 32 + c4];
    int kq = c4 >> 3, c8 = c4 & 7;
    float* dst = g_Ab + (size_t)slab * 16384 + kq * 4096
               + cell * 32 + (swz8(c8, cell & 7) >> 2);
    atomicAdd(dst + 0, v.x);
    atomicAdd(dst + 1, v.y);
    atomicAdd(dst + 2, v.z);
    atomicAdd(dst + 3, v.w);
    if (c4 == 0) atomicAdd(&g_occ[slab * XQ + cell], 1);
}

// ---------------- K2: occ-2, quarter-stage bulk-copy tf32 conv ----------------
// Stage (40KB): A-quarter [0,16K), W [16K,40K) (kx stride 8K). 2 buffers.
// LPT launch order: heavy CTAs (odd oy => nky=2; interior ot => 3 kt-taps) first.
#define STG 40960
#define CONV_DYN_SMEM (2 * STG)

__global__ void __launch_bounds__(256, 2) k_conv(float* __restrict__ out) {
    extern __shared__ char smem[];
    __shared__ __align__(8) uint64_t mb[4];   // full0, full1, empty0, empty1
    const uint32_t sb = smem_u32(smem);
    const uint32_t mbF0 = smem_u32(&mb[0]), mbF1 = smem_u32(&mb[1]);
    const uint32_t mbE0 = smem_u32(&mb[2]), mbE1 = smem_u32(&mb[3]);
    const int tid = threadIdx.x, wid = tid >> 5, lane = tid & 31;
    const int half = wid & 1, wm = wid >> 1;

    const int bid = blockIdx.x;
    // LPT remap: odd output rows first (2 y-taps), even rows last
    const int oyIdx = bid % YOQ;
    const int oy = (oyIdx < 127) ? (2 * oyIdx + 1) : (2 * (oyIdx - 127));
    // interior ot first (3 t-taps), edges (ot=0,7) last
    const int bt = bid / YOQ;
    const int b = bt >> 3;
    const int oti = bt & 7;
    const int ot = (oti < 6) ? (oti + 1) : ((oti == 6) ? 0 : 7);

    // y taps
    int nky, cys[2], kys[2];
    if ((oy & 1) == 0) { nky = 1; cys[0] = oy >> 1;       kys[0] = 1; }
    else               { nky = 2; cys[0] = (oy + 1) >> 1; kys[0] = 0;
                                  cys[1] = (oy - 1) >> 1; kys[1] = 2; }

    // iteration list
    int nIter = 0, slabI[6], ktkyI[6];
    for (int kt = 0; kt < 3; kt++) {
        int ctv = ot + 1 - kt;
        if (ctv < 0 || ctv >= TQ) continue;
        for (int yt = 0; yt < nky; yt++) {
            slabI[nIter] = (b * TQ + ctv) * YQ + cys[yt];
            ktkyI[nIter] = kt * 3 + kys[yt];
            nIter++;
        }
    }
    const int nStage = nIter * 4;

    if (tid == 0) {
        MBARRIER_INIT(mbF0, 1); MBARRIER_INIT(mbF1, 1);
        MBARRIER_INIT(mbE0, 8); MBARRIER_INIT(mbE1, 8);
    }
    __syncthreads();

    // ldmatrix geometry (128B rows)
    const int r0 = wm << 5;
    const int matL = lane >> 3, rr = lane & 7;
    const int cSel = matL >> 1;
    int rowA0[2];
    rowA0[0] = r0 + rr + ((matL & 1) << 3);
    rowA0[1] = rowA0[0] + 16;
    const uint32_t bA0[2] = { (uint32_t)rowA0[0] * 128, (uint32_t)rowA0[1] * 128 };
    const uint32_t bA1[2] = { bA0[0] + 128, bA0[1] + 128 };   // rows +1 (row 128 garbage, masked)
    const int rs0[2] = { rowA0[0] & 7, rowA0[1] & 7 };
    const int rs1[2] = { (rowA0[0] + 1) & 7, (rowA0[1] + 1) & 7 };
    const int rowB = half * 32 + rr + ((matL & 1) << 3);
    const uint32_t bB0 = (uint32_t)rowB * 128;
    const uint32_t bB1 = bB0 + 16 * 128;
    const int rsB = rowB & 7;

    float accE[2][4][4], accO[2][4][4];
#pragma unroll
    for (int mt = 0; mt < 2; mt++)
#pragma unroll
        for (int i = 0; i < 4; i++)
#pragma unroll
            for (int j = 0; j < 4; j++) { accE[mt][i][j] = 0.f; accO[mt][i][j] = 0.f; }

#define FETCH(ST, DST, MBAR) do { \
    int _it = (ST) >> 2, _kq = (ST) & 3; \
    MBARRIER_EXPECT_TX(MBAR, STG); \
    bulkcp((DST),         (const char*)g_Ab + (size_t)slabI[_it] * 65536 + _kq * 16384, 16384, MBAR); \
    bulkcp((DST) + 16384, g_Wt + (size_t)(ktkyI[_it] * 4 + _kq) * 24576,   24576, MBAR); \
} while (0)

    if (tid == 0) {
        FETCH(0, sb, mbF0);
        FETCH(1, sb + STG, mbF1);
    }

    int phF0 = 0, phF1 = 0, phE0 = 0, phE1 = 0;
    for (int st = 0; st < nStage; st++) {
        const int buf = st & 1;
        const uint32_t S = sb + (uint32_t)buf * STG;
        if (buf) { MBARRIER_WAIT_PARITY(mbF1, phF1); phF1 ^= 1; }
        else     { MBARRIER_WAIT_PARITY(mbF0, phF0); phF0 ^= 1; }

        const uint32_t W0 = S + 16384;            // kx=0
        const uint32_t W1 = S + 16384 + 8192;     // kx=1
        const uint32_t W2 = S + 16384 + 16384;    // kx=2
#pragma unroll
        for (int s = 0; s < 4; s++) {
            int ck = 2 * s + cSel;
            uint32_t a0[2][4], a1[2][4];
            uint32_t b1f[8], b2f[8], b0f[8];
#pragma unroll
            for (int mt = 0; mt < 2; mt++) {
                ldsm4(a0[mt], S + bA0[mt] + swz8(ck, rs0[mt]));
                ldsm4(a1[mt], S + bA1[mt] + swz8(ck, rs1[mt]));
            }
            {
                uint32_t ob = swz8(ck, rsB);
                ldsm4(b1f,     W1 + bB0 + ob);
                ldsm4(b1f + 4, W1 + bB1 + ob);
                ldsm4(b2f,     W2 + bB0 + ob);
                ldsm4(b2f + 4, W2 + bB1 + ob);
                ldsm4(b0f,     W0 + bB0 + ob);
                ldsm4(b0f + 4, W0 + bB1 + ob);
            }
#pragma unroll
            for (int j2 = 0; j2 < 2; j2++)
#pragma unroll
                for (int mt = 0; mt < 2; mt++) {
                    mma_tf32(accE[mt][2 * j2],     a0[mt], b1f[4 * j2],     b1f[4 * j2 + 2]);
                    mma_tf32(accE[mt][2 * j2 + 1], a0[mt], b1f[4 * j2 + 1], b1f[4 * j2 + 3]);
                }
#pragma unroll
            for (int j2 = 0; j2 < 2; j2++)
#pragma unroll
                for (int mt = 0; mt < 2; mt++) {
                    mma_tf32(accO[mt][2 * j2],     a0[mt], b2f[4 * j2],     b2f[4 * j2 + 2]);
                    mma_tf32(accO[mt][2 * j2 + 1], a0[mt], b2f[4 * j2 + 1], b2f[4 * j2 + 3]);
                }
#pragma unroll
            for (int j2 = 0; j2 < 2; j2++)
#pragma unroll
                for (int mt = 0; mt < 2; mt++) {
                    mma_tf32(accO[mt][2 * j2],     a1[mt], b0f[4 * j2],     b0f[4 * j2 + 2]);
                    mma_tf32(accO[mt][2 * j2 + 1], a1[mt], b0f[4 * j2 + 1], b0f[4 * j2 + 3]);
                }
        }
        __syncwarp();
        if (lane == 0) MBARRIER_ARRIVE(buf ? mbE1 : mbE0);
        if (tid == 0 && st + 2 < nStage) {
            if (buf) { MBARRIER_WAIT_PARITY(mbE1, phE1); phE1 ^= 1; }
            else     { MBARRIER_WAIT_PARITY(mbE0, phE0); phE0 ^= 1; }
            FETCH(st + 2, S, buf ? mbF1 : mbF0);
        }
    }
#undef FETCH

    // ---------------- epilogue: stores + stats ----------------
    const int g = lane >> 2;
    const int n0base = (lane & 3) * 2;
    const int sbase = ((b * TQ + ot) * YOQ + oy) * XOQ;

    float sl[8] = {0,0,0,0,0,0,0,0}, ql[8] = {0,0,0,0,0,0,0,0};
#pragma unroll
    for (int mt = 0; mt < 2; mt++) {
        const int mA = r0 + 16 * mt + g;
        const int mB = mA + 8;
        const bool oddBvalid = (mB != 127);      // ox=255 doesn't exist
#pragma unroll
        for (int nt = 0; nt < 4; nt++) {
            int n0 = half * 32 + nt * 8 + n0base;
            *(float2*)(out + (size_t)(sbase + 2 * mA) * COUTQ + n0) =
                make_float2(accE[mt][nt][0], accE[mt][nt][1]);
            *(float2*)(out + (size_t)(sbase + 2 * mB) * COUTQ + n0) =
                make_float2(accE[mt][nt][2], accE[mt][nt][3]);
            *(float2*)(out + (size_t)(sbase + 2 * mA + 1) * COUTQ + n0) =
                make_float2(accO[mt][nt][0], accO[mt][nt][1]);
            if (oddBvalid)
                *(float2*)(out + (size_t)(sbase + 2 * mB + 1) * COUTQ + n0) =
                    make_float2(accO[mt][nt][2], accO[mt][nt][3]);
#pragma unroll
            for (int c = 0; c < 2; c++) {
                float e0 = accE[mt][nt][c], e2 = accE[mt][nt][2 + c];
                float o0 = accO[mt][nt][c], o2 = oddBvalid ? accO[mt][nt][2 + c] : 0.f;
                sl[nt * 2 + c] += e0 + e2 + o0 + o2;
                ql[nt * 2 + c] += e0 * e0 + e2 * e2 + o0 * o0 + o2 * o2;
            }
        }
    }
#pragma unroll
    for (int d = 4; d <= 16; d <<= 1) {
#pragma unroll
        for (int i = 0; i < 8; i++) {
            sl[i] += __shfl_xor_sync(0xffffffffu, sl[i], d);
            ql[i] += __shfl_xor_sync(0xffffffffu, ql[i], d);
        }
    }
    __syncthreads();                          // pipeline drained; reuse smem
    float* redS = (float*)smem;               // [8 warps][4][8]
    float* redQ = (float*)(smem + 8 * 4 * 8 * 4);
    if (lane < 4) {
#pragma unroll
        for (int i = 0; i < 8; i++) {
            redS[(wid * 4 + lane) * 8 + i] = sl[i];
            redQ[(wid * 4 + lane) * 8 + i] = ql[i];
        }
    }
    __syncthreads();
    if (tid < COUTQ) {
        int h2 = tid >> 5, nt = (tid >> 3) & 3, c4 = (tid >> 1) & 3, cc = tid & 1;
        int idx = nt * 2 + cc;
        float S = 0.f, Q = 0.f;
#pragma unroll
        for (int wmx = 0; wmx < 4; wmx++) {
            int w = wmx * 2 + h2;
            S += redS[(w * 4 + c4) * 8 + idx];
            Q += redQ[(w * 4 + c4) * 8 + idx];
        }
        atomicAdd(&g_sum[tid], S);
        atomicAdd(&g_sumsq[tid], Q);
    }

    // ---------------- active-site mask ----------------
    bool act = false;
    if (tid < XOQ) {
        int ox2 = tid;
        int xc[2]; int nxc = 0;
        if ((ox2 & 1) == 0) { xc[nxc++] = ox2 >> 1; }
        else {
            int c0 = (ox2 + 1) >> 1;
            if (c0 < XQ) xc[nxc++] = c0;
            xc[nxc++] = (ox2 - 1) >> 1;
        }
        for (int kt = 0; kt < 3 && !act; kt++) {
            int ctv = ot + 1 - kt;
            if (ctv < 0 || ctv >= TQ) continue;
            for (int yt = 0; yt < nky && !act; yt++) {
                int cb2 = ((b * TQ + ctv) * YQ + cys[yt]) * XQ;
                for (int xi = 0; xi < nxc; xi++)
                    if (g_occ[cb2 + xc[xi]] > 0) { act = true; break; }
            }
        }
        g_mask[sbase + ox2] = act ? 1 : 0;
    }
    unsigned bal = __ballot_sync(0xffffffffu, act);
    if (lane == 0 && bal) atomicAdd(&g_nactive, __popc(bal));
}

// ---------------- K3: normalize + relu + mask (BN fold done in-block) ----------------
__global__ void k_final(float* __restrict__ out,
                        const float* __restrict__ gamma, const float* __restrict__ beta) {
    __shared__ float s_scale[COUTQ], s_shift[COUTQ];
    int tid = threadIdx.x;
    if (tid < COUTQ) {
        float n = (float)max(g_nactive, 1);
        float mean = g_sum[tid] / n;
        float var  = g_sumsq[tid] / n - mean * mean;
        float rstd = rsqrtf(var + EPSQ);
        float sc   = rstd * gamma[tid];
        s_scale[tid] = sc;
        s_shift[tid] = beta[tid] - mean * sc;
    }
    __syncthreads();
    int i = blockIdx.x * 256 + tid;
    int site = i >> 4;
    int cg   = i & 15;
    float4 v  = ((float4*)out)[i];
    float4 sc = *(const float4*)(s_scale + cg * 4);
    float4 sh = *(const float4*)(s_shift + cg * 4);
    float  m  = g_mask[site] ? 1.f : 0.f;
    v.x = fmaxf(v.x * sc.x + sh.x, 0.f) * m;
    v.y = fmaxf(v.y * sc.y + sh.y, 0.f) * m;
    v.z = fmaxf(v.z * sc.z + sh.z, 0.f) * m;
    v.w = fmaxf(v.w * sc.w + sh.w, 0.f) * m;
    ((float4*)out)[i] = v;
}

// ---------------- launch ----------------
extern "C" void kernel_launch(void* const* d_in, const int* in_sizes, int n_in,
                              void* d_out, int out_size) {
    const float* feats  = (const float*)d_in[0];
    const float* weight = (const float*)d_in[1];
    const float* gamma  = (const float*)d_in[2];
    const float* beta   = (const float*)d_in[3];
    const int*   cb     = (const int*)d_in[4];
    const int*   ct     = (const int*)d_in[5];
    const int*   cy     = (const int*)d_in[6];
    const int*   cx     = (const int*)d_in[7];
    float* out = (float*)d_out;

    cudaFuncSetAttribute(k_conv, cudaFuncAttributeMaxDynamicSharedMemorySize, CONV_DYN_SMEM);

    k_zero<<<NCELL * CIN / 4 / 256, 256>>>(weight);
    k_scatter<<<NPTS * 32 / 256, 256>>>(feats, cb, ct, cy, cx);
    k_conv<<<BQ * TQ * YOQ, 256, CONV_DYN_SMEM>>>(out);
    k_final<<<NSITE * 16 / 256, 256>>>(out, gamma, beta);
}